// round 13
// baseline (speedup 1.0000x reference)
#include <cuda_runtime.h>
#include <cstdint>

// x [4,512,128] f32, y [512,128] f32 -> out [4,512,512,3] f32 (cos, L1, L2)
#define R_TOTAL 2048
#define C_TOTAL 512
#define D_DIM   128
#define NDD2    64              // packed-pair (2 D-values) steps

#define BM 64                   // x rows per block
#define BN 64                   // y rows per block
#define XTS 65                  // xsT stride per dd2, in u64 (64 rows + 1 pad)
#define YTS 66                  // ysT stride per dd2, in u64 (64 rows + 2 pad, 16B align)
#define NORM_OFF (NDD2 * XTS + NDD2 * YTS)          // u64 offset of norm area
#define SMEM_BYTES (NORM_OFF * 8 + 128 * 2 * 4)     // 67.1 KB per CTA

typedef unsigned long long u64;
struct __align__(16) ull2 { u64 x, y; };

// ---------------- packed f32x2 helpers ----------------
__device__ __forceinline__ u64 ffma2(u64 a, u64 b, u64 c) {
    u64 d;
    asm("fma.rn.f32x2 %0, %1, %2, %3;" : "=l"(d) : "l"(a), "l"(b), "l"(c));
    return d;
}
__device__ __forceinline__ u64 fadd2(u64 a, u64 b) {
    u64 d;
    asm("add.rn.f32x2 %0, %1, %2;" : "=l"(d) : "l"(a), "l"(b));
    return d;
}
__device__ __forceinline__ float f2lo(u64 d) { return __uint_as_float((unsigned)(d & 0xFFFFFFFFu)); }
__device__ __forceinline__ float f2hi(u64 d) { return __uint_as_float((unsigned)(d >> 32)); }
__device__ __forceinline__ u64 pack2(float lo, float hi) {
    return ((u64)__float_as_uint(hi) << 32) | (u64)__float_as_uint(lo);
}

// ---------------- fused distance kernel ----------------
// 512 threads, 2 CTAs/SM (8 warps/SMSP). tx = t&31 -> y cols {2tx,2tx+1};
// ty = t>>5 -> x rows ty+16i (i<4). y tile NEGATED: diff = x + (-y) = FADD2.
__global__ void __launch_bounds__(512, 2)
dist_kernel(const float* __restrict__ x, const float* __restrict__ y,
            float* __restrict__ out) {
    extern __shared__ __align__(16) u64 sm64[];
    u64* xsT = sm64;                    // [NDD2][XTS]
    u64* ysT = sm64 + NDD2 * XTS;       // [NDD2][YTS] (holds -y)
    float* nsq = reinterpret_cast<float*>(sm64 + NORM_OFF);  // [128]: 64 x + 64 y
    float* nrn = nsq + 128;

    const int R0 = blockIdx.x * BM;     // grid.x = 32
    const int C0 = blockIdx.y * BN;     // grid.y = 8
    const int t  = threadIdx.x;
    const int tx = t & 31;
    const int ty = t >> 5;

    // ---- stage x tile (64 rows x 128 cols): 4 float4 per thread
    #pragma unroll
    for (int s = 0; s < 4; s++) {
        int idx  = t + 512 * s;         // 0..2047
        int row  = idx >> 5;            // 0..63
        int col4 = idx & 31;
        float4 v = *reinterpret_cast<const float4*>(
            x + (size_t)(R0 + row) * D_DIM + col4 * 4);
        xsT[(2 * col4) * XTS + row]     = pack2(v.x, v.y);
        xsT[(2 * col4 + 1) * XTS + row] = pack2(v.z, v.w);
    }
    // ---- stage y tile NEGATED (64 rows x 128 cols): 4 float4 per thread
    #pragma unroll
    for (int s = 0; s < 4; s++) {
        int idx  = t + 512 * s;         // 0..2047
        int row  = idx >> 5;            // 0..63
        int col4 = idx & 31;
        float4 v = *reinterpret_cast<const float4*>(
            y + (size_t)(C0 + row) * D_DIM + col4 * 4);
        ysT[(2 * col4) * YTS + row]     = pack2(-v.x, -v.y);
        ysT[(2 * col4 + 1) * YTS + row] = pack2(-v.z, -v.w);
    }
    __syncthreads();

    // ---- fused norms ((-y)^2 == y^2): t<64 -> x row t; 64<=t<128 -> y row t-64
    if (t < 128) {
        const u64* base; int stride;
        if (t < 64) { base = xsT + t;        stride = XTS; }
        else        { base = ysT + (t - 64); stride = YTS; }
        u64 a = 0ULL;
        #pragma unroll 8
        for (int dd2 = 0; dd2 < NDD2; dd2++) {
            u64 v = base[dd2 * stride];
            a = ffma2(v, v, a);
        }
        float s = f2lo(a) + f2hi(a);
        nsq[t] = s;
        nrn[t] = rsqrtf(s);
    }
    __syncthreads();

    const u64 ABSM = 0x7FFFFFFF7FFFFFFFULL;   // packed abs mask

    u64 acc1[4][2];   // packed L1 sums   [x-row i][y-col j]
    u64 acc2[4][2];   // packed sum of squares
    #pragma unroll
    for (int i = 0; i < 4; i++)
        #pragma unroll
        for (int j = 0; j < 2; j++) { acc1[i][j] = 0ULL; acc2[i][j] = 0ULL; }

    const u64*  px = xsT + ty;                                    // x rows ty+16i
    const ull2* py = reinterpret_cast<const ull2*>(ysT + 2 * tx); // y cols 2tx,2tx+1

    #pragma unroll 8
    for (int dd2 = 0; dd2 < NDD2; dd2++) {
        u64 xv[4];
        #pragma unroll
        for (int i = 0; i < 4; i++) xv[i] = px[16 * i];   // LDS.64 broadcast
        ull2 yv = *py;                                    // LDS.128 contiguous

        #pragma unroll
        for (int i = 0; i < 4; i++) {
            u64 e0 = fadd2(xv[i], yv.x);                  // x - y, col 2tx (rt=2)
            u64 e1 = fadd2(xv[i], yv.y);                  // col 2tx+1
            acc2[i][0] = ffma2(e0, e0, acc2[i][0]);
            acc2[i][1] = ffma2(e1, e1, acc2[i][1]);
            acc1[i][0] = fadd2(acc1[i][0], e0 & ABSM);
            acc1[i][1] = fadd2(acc1[i][1], e1 & ABSM);
        }

        px += XTS;
        py += YTS / 2;
    }

    // ---- epilogue: cos / p1 / p2; 6 consecutive floats per row -> 3x STG.64
    #pragma unroll
    for (int i = 0; i < 4; i++) {
        int lrow = ty + 16 * i;
        int gr = R0 + lrow;
        float xsq = nsq[lrow];
        float xrn = nrn[lrow];
        float o[6];
        #pragma unroll
        for (int j = 0; j < 2; j++) {
            int lcol = 2 * tx + j;
            float s2 = f2lo(acc2[i][j]) + f2hi(acc2[i][j]);
            float s1 = f2lo(acc1[i][j]) + f2hi(acc1[i][j]);
            float p2 = sqrtf(fmaxf(s2, 0.0f));
            float dot = 0.5f * (xsq + nsq[64 + lcol] - s2);
            float cosv = dot * xrn * nrn[64 + lcol];
            o[3 * j + 0] = cosv;
            o[3 * j + 1] = s1;
            o[3 * j + 2] = p2;
        }
        // base = (gr*512 + C0 + 2tx)*3 : even index -> 8B aligned, 6 floats
        size_t base = ((size_t)gr * C_TOTAL + C0 + 2 * tx) * 3;
        float2* dst = reinterpret_cast<float2*>(out + base);
        dst[0] = make_float2(o[0], o[1]);
        dst[1] = make_float2(o[2], o[3]);
        dst[2] = make_float2(o[4], o[5]);
    }
}

extern "C" void kernel_launch(void* const* d_in, const int* in_sizes, int n_in,
                              void* d_out, int out_size) {
    const float* x = (const float*)d_in[0];
    const float* y = (const float*)d_in[1];
    float* out = (float*)d_out;

    static int attr_done = 0;
    if (!attr_done) {
        cudaFuncSetAttribute(dist_kernel,
                             cudaFuncAttributeMaxDynamicSharedMemorySize, SMEM_BYTES);
        cudaFuncSetAttribute(dist_kernel,
                             cudaFuncAttributePreferredSharedMemoryCarveout, 100);
        attr_done = 1;
    }

    dim3 grid(R_TOTAL / BM, C_TOTAL / BN);   // 32 x 8 = 256 blocks, 2 CTA/SM -> 1 wave
    dist_kernel<<<grid, 512, SMEM_BYTES>>>(x, y, out);
}